// round 13
// baseline (speedup 1.0000x reference)
#include <cuda_runtime.h>
#include <cuda_bf16.h>
#include <cuda_fp16.h>
#include <math.h>
#include <cstdint>

#define NN 2048
#define CC 16
#define FF 1024
#define NHEADS 4
#define KF 4096
#define EE 16384
#define NPIX 131072
#define BNEPS 1e-5f
#define KA 1024

// ---------------- scratch (static device memory; no allocation) ----------------
__device__ __half d_Af[NN * KA];
__device__ __half d_Blh[KF * KA];
__device__ __half d_Brh[KF * KA];
__device__ __half d_xl[NN * KF];
__device__ __half d_xr[NN * KF];
__device__ float d_Sx[16];
__device__ float d_Sxx[136];
__device__ float d_A[256];
__device__ float d_dv[16];
__device__ int   d_cnt[NN];
__device__ int   d_rowstart[NN + 1];
__device__ int   d_cursor[NN];
__device__ int   d_esrc[EE + NN];
__device__ float d_b2sum[16], d_b2sq[16];
__device__ int   d_tick;                          // zero at start; self-reset

// ---------------- helpers ----------------
__device__ __forceinline__ uint32_t smem_u32(const void* p) {
    uint32_t a;
    asm("{ .reg .u64 t; cvta.to.shared.u64 t, %1; cvt.u32.u64 %0, t; }" : "=r"(a) : "l"(p));
    return a;
}
__device__ __forceinline__ void cp16(uint32_t dst, const void* src) {
    asm volatile("cp.async.cg.shared.global [%0], [%1], 16;" :: "r"(dst), "l"(src) : "memory");
}
__device__ __forceinline__ void ldm4(uint32_t* r, uint32_t addr) {
    asm volatile("ldmatrix.sync.aligned.m8n8.x4.shared.b16 {%0,%1,%2,%3}, [%4];"
                 : "=r"(r[0]), "=r"(r[1]), "=r"(r[2]), "=r"(r[3]) : "r"(addr));
}
__device__ __forceinline__ void mma16816(float* d, const uint32_t* a, uint32_t b0, uint32_t b1) {
    asm volatile("mma.sync.aligned.m16n8k16.row.col.f32.f16.f16.f32 "
                 "{%0,%1,%2,%3}, {%4,%5,%6,%7}, {%8,%9}, {%0,%1,%2,%3};"
                 : "+f"(d[0]), "+f"(d[1]), "+f"(d[2]), "+f"(d[3])
                 : "r"(a[0]), "r"(a[1]), "r"(a[2]), "r"(a[3]), "r"(b0), "r"(b1));
}

// ---------------- pre1: stats (b<256) || hist (b<320); LAST block does bnfold + scan ----------------
__global__ __launch_bounds__(256) void k_pre1(const float* __restrict__ x,
                                              const int* __restrict__ ei,
                                              const float* __restrict__ w1, const float* __restrict__ b1,
                                              const float* __restrict__ g1, const float* __restrict__ be1) {
    int b = blockIdx.x;
    int t = threadIdx.x;
    if (b < 256) {
        __shared__ float sm[16][513];
        int base = b * 512;
        for (int i = t; i < 16 * 512; i += 256) {
            int c = i >> 9, s = i & 511;
            int q = base + s;
            sm[c][s] = x[(q >> 6) * 1024 + c * 64 + (q & 63)];
        }
        __syncthreads();
        if (t < 16) {
            float acc = 0.f;
            #pragma unroll 8
            for (int s = 0; s < 512; s++) acc += sm[t][s];
            atomicAdd(&d_Sx[t], acc);
        } else if (t < 152) {
            int p = t - 16;
            int c = 0, r = p;
            while (r >= 16 - c) { r -= 16 - c; c++; }
            int c2 = c + r;
            float acc = 0.f;
            #pragma unroll 8
            for (int s = 0; s < 512; s++) acc += sm[c][s] * sm[c2][s];
            atomicAdd(&d_Sxx[p], acc);
        }
    } else {
        int e = (b - 256) * 256 + t;
        if (e < EE) {
            int s = ei[e], d = ei[EE + e];
            if (s != d) atomicAdd(&d_cnt[d], 1);
        }
    }
    __shared__ int isLast;
    __syncthreads();
    if (t == 0) {
        __threadfence();
        int done = atomicAdd(&d_tick, 1);
        isLast = (done == 319);
        if (isLast) d_tick = 0;
    }
    __syncthreads();
    if (!isLast) return;
    __threadfence();

    {
        __shared__ float mx[16], cov[16][16];
        if (t < 16) mx[t] = d_Sx[t] * (1.0f / NPIX);
        __syncthreads();
        if (t < 136) {
            int c = 0, r = t;
            while (r >= 16 - c) { r -= 16 - c; c++; }
            int c2 = c + r;
            float cv = d_Sxx[t] * (1.0f / NPIX) - mx[c] * mx[c2];
            cov[c][c2] = cv; cov[c2][c] = cv;
        }
        __syncthreads();
        if (t < 16) d_Sx[t] = 0.f;
        if (t < 136) d_Sxx[t] = 0.f;
        int o = t >> 4, c = t & 15;
        float wc = w1[o * 16 + c];
        float pm = wc * mx[c];
        float pv = 0.f;
        #pragma unroll
        for (int c2 = 0; c2 < 16; c2++) pv += w1[o * 16 + c2] * cov[c][c2];
        pv *= wc;
        #pragma unroll
        for (int off = 8; off > 0; off >>= 1) {
            pm += __shfl_down_sync(0xffffffffu, pm, off, 16);
            pv += __shfl_down_sync(0xffffffffu, pv, off, 16);
        }
        float m = __shfl_sync(0xffffffffu, pm, (t & 16), 32) + b1[o];
        float var = __shfl_sync(0xffffffffu, pv, (t & 16), 32);
        float rs = rsqrtf(var + BNEPS) * g1[o];
        d_A[o * 16 + c] = wc * rs;
        if (c == 0) d_dv[o] = (b1[o] - m) * rs + be1[o];
    }
    __syncthreads();

    {
        __shared__ int wsum[8];
        int lane = t & 31, warp = t >> 5;
        int a[8], s = 0;
        #pragma unroll
        for (int k = 0; k < 8; k++) {
            a[k] = d_cnt[8 * t + k] + 1;
            s += a[k];
            d_cnt[8 * t + k] = 0;
        }
        int incl = s;
        #pragma unroll
        for (int off = 1; off < 32; off <<= 1) {
            int v = __shfl_up_sync(0xffffffffu, incl, off);
            if (lane >= off) incl += v;
        }
        if (lane == 31) wsum[warp] = incl;
        __syncthreads();
        if (t == 0) {
            int run = 0;
            #pragma unroll
            for (int w = 0; w < 8; w++) { run += wsum[w]; wsum[w] = run; }
        }
        __syncthreads();
        int base = (warp > 0) ? wsum[warp - 1] : 0;
        int running = base + incl - s;
        #pragma unroll
        for (int k = 0; k < 8; k++) {
            int idx = 8 * t + k;
            d_rowstart[idx] = running;
            d_cursor[idx] = running;
            running += a[k];
        }
        if (t == 255) d_rowstart[2048] = running;
    }
}

// ---------------- pre3: scatter (b<72) || yf (b<584) || convB wl (b<4680) || convB wr ----------------
__device__ __forceinline__ void convB_body(const float* __restrict__ w,
                                           __half* __restrict__ Bf,
                                           int bx, int by, int t) {
    __shared__ float ts[32][33];
    int nb = bx * 32;
    int kb = by * 32;
    int col = t & 31, trow = t >> 5;
    #pragma unroll
    for (int i = 0; i < 4; i++) {
        int r = trow + i * 8;
        ts[r][col] = w[(size_t)(kb + r) * 4096 + nb + col];
    }
    __syncthreads();
    int nloc = t >> 3, kq = (t & 7) * 4;
    __half hv[4];
    #pragma unroll
    for (int j = 0; j < 4; j++) hv[j] = __float2half(ts[kq + j][nloc]);
    size_t base = (size_t)(nb + nloc) * KA + kb + kq;
    *(uint2*)(Bf + base) = *(uint2*)hv;
}

__global__ __launch_bounds__(256) void k_pre3(const int* __restrict__ ei,
                                              const float* __restrict__ x,
                                              const float* __restrict__ wl,
                                              const float* __restrict__ wr) {
    int b = blockIdx.x;
    int t = threadIdx.x;
    if (b < 72) {
        if (b == 0 && t < 16) { d_b2sum[t] = 0.f; d_b2sq[t] = 0.f; }
        int i = b * 256 + t;
        if (i < NN) {
            int pos = atomicAdd(&d_cursor[i], 1);
            d_esrc[pos] = i;
        } else if (i < NN + EE) {
            int e = i - NN;
            int s = ei[e], d = ei[EE + e];
            if (s != d) { int pos = atomicAdd(&d_cursor[d], 1); d_esrc[pos] = s; }
        }
    } else if (b < 584) {
        __shared__ float As[256], dvs[16];
        if (t < 256) As[t] = d_A[t];
        if (t < 16) dvs[t] = d_dv[t];
        __syncthreads();
        int q = (b - 72) * 256 + t;
        int n = q >> 6, p = q & 63;
        float xv[16];
        #pragma unroll
        for (int c = 0; c < 16; c++) xv[c] = x[n * 1024 + c * 64 + p];
        #pragma unroll
        for (int o = 0; o < 16; o++) {
            float s = dvs[o];
            #pragma unroll
            for (int c = 0; c < 16; c++) s += As[o * 16 + c] * xv[c];
            int f = o * 64 + p;
            d_Af[(size_t)n * KA + f] = __float2half(s);
        }
    } else if (b < 4680) {
        int i = b - 584;
        convB_body(wl, d_Blh, i & 127, i >> 7, t);
    } else {
        int i = b - 4680;
        convB_body(wr, d_Brh, i & 127, i >> 7, t);
    }
}

// ---------------- mma.sync fp16 GEMM: 128x256 tile, 512 thr, K-chunk 128, 2-stage ----------------
#define STAGE_B 98304
#define GSM_TOTAL (2 * STAGE_B)

#define ISSUE_CHUNK(kb, buf) do {                                               \
    uint32_t sA_ = sbase + (buf) * STAGE_B;                                     \
    uint32_t sB_ = sA_ + 32768;                                                 \
    _Pragma("unroll")                                                           \
    for (int i_ = 0; i_ < 4; i_++) {                                            \
        int id_ = t + i_ * 512, r_ = id_ >> 4, c_ = id_ & 15;                   \
        cp16(sA_ + r_ * 256 + ((c_ >> 3) << 7) + ((((c_ & 7) ^ (r_ & 7))) << 4),\
             Ag + (size_t)r_ * KA + (kb) * 128 + c_ * 8);                       \
    }                                                                           \
    _Pragma("unroll")                                                           \
    for (int i_ = 0; i_ < 8; i_++) {                                            \
        int id_ = t + i_ * 512, r_ = id_ >> 4, c_ = id_ & 15;                   \
        cp16(sB_ + r_ * 256 + ((c_ >> 3) << 7) + ((((c_ & 7) ^ (r_ & 7))) << 4),\
             Bg + (size_t)r_ * KA + (kb) * 128 + c_ * 8);                       \
    }                                                                           \
    asm volatile("cp.async.commit_group;" ::: "memory");                        \
} while (0)

__global__ __launch_bounds__(512) void k_gemm(const float* __restrict__ biasl,
                                              const float* __restrict__ biasr) {
    extern __shared__ char smem[];
    uint32_t sbase = smem_u32(smem);
    int t = threadIdx.x, lane = t & 31, wid = t >> 5;
    int wm = wid & 3, wn = wid >> 2;
    int bm = blockIdx.y * 128;
    int bx = blockIdx.x;
    int isR = bx >= 16;
    int bn = (bx - (isR ? 16 : 0)) * 256;

    const __half* Ag = d_Af + (size_t)bm * KA;
    const __half* Bg = (isR ? d_Brh : d_Blh) + (size_t)bn * KA;
    const float* bias = isR ? biasr : biasl;
    __half* C = isR ? d_xr : d_xl;

    float acc[2][8][4];
    #pragma unroll
    for (int mi = 0; mi < 2; mi++)
        #pragma unroll
        for (int nj = 0; nj < 8; nj++)
            #pragma unroll
            for (int k = 0; k < 4; k++) acc[mi][nj][k] = 0.f;

    ISSUE_CHUNK(0, 0);
    ISSUE_CHUNK(1, 1);

    int g = lane >> 3, li = lane & 7;
    int arow = wm * 32 + (g & 1) * 8 + li;
    int brow = wn * 64 + (g >> 1) * 8 + li;
    int aun = (g >> 1);
    int bun = (g & 1);

    for (int kb = 0; kb < 8; kb++) {
        asm volatile("cp.async.wait_group 1;" ::: "memory");
        __syncthreads();
        uint32_t sA = sbase + (kb & 1) * STAGE_B;
        uint32_t sB = sA + 32768;
        #pragma unroll
        for (int ks = 0; ks < 8; ks++) {
            uint32_t af[2][4], bf[4][4];
            #pragma unroll
            for (int mi = 0; mi < 2; mi++) {
                int row = arow + mi * 16;
                int unit = ks * 2 + aun;
                ldm4(af[mi], sA + row * 256 + ((unit >> 3) << 7) + ((((unit & 7) ^ (row & 7))) << 4));
            }
            #pragma unroll
            for (int nt = 0; nt < 4; nt++) {
                int row = brow + nt * 16;
                int unit = ks * 2 + bun;
                ldm4(bf[nt], sB + row * 256 + ((unit >> 3) << 7) + ((((unit & 7) ^ (row & 7))) << 4));
            }
            #pragma unroll
            for (int mi = 0; mi < 2; mi++)
                #pragma unroll
                for (int nt = 0; nt < 4; nt++) {
                    mma16816(acc[mi][nt * 2 + 0], af[mi], bf[nt][0], bf[nt][1]);
                    mma16816(acc[mi][nt * 2 + 1], af[mi], bf[nt][2], bf[nt][3]);
                }
        }
        __syncthreads();
        if (kb + 2 < 8) { ISSUE_CHUNK(kb + 2, kb & 1); }
        else { asm volatile("cp.async.commit_group;" ::: "memory"); }
    }

    #pragma unroll
    for (int mi = 0; mi < 2; mi++) {
        int gm0 = bm + wm * 32 + mi * 16 + (lane >> 2);
        #pragma unroll
        for (int nj = 0; nj < 8; nj++) {
            int gn = bn + wn * 64 + nj * 8 + (lane & 3) * 2;
            float2 bv = *(const float2*)(bias + gn);
            __half2 h0 = __floats2half2_rn(acc[mi][nj][0] + bv.x, acc[mi][nj][1] + bv.y);
            __half2 h1 = __floats2half2_rn(acc[mi][nj][2] + bv.x, acc[mi][nj][3] + bv.y);
            *(__half2*)(C + (size_t)gm0 * 4096 + gn) = h0;
            *(__half2*)(C + (size_t)(gm0 + 8) * 4096 + gn) = h1;
        }
    }
}

// ---------------- fused GAT: chunked smem-staged edges (8/chunk) + conv2 + BN2 stats ----------------
// smem layout (bytes):
//  [0,8192)      xr_s    (4096 half)
//  [8192,24576)  att_s   (2048 float2)   -- aliased by gs (4096 float) after edge loop
//  [24576,90112) xls     (8 edges x 8192) -- aliased by w2s (1024 float) after edge loop
//  [90112,90240) logit_s (32 float)
//  [90240,90304) ssum    (16 float)
//  [90304,90368) ssq     (16 float)
#define GAT_SMEM 90368
__global__ __launch_bounds__(256) void k_gat(const float* __restrict__ att,
                                             const float* __restrict__ biasg,
                                             const float* __restrict__ w2,
                                             const float* __restrict__ b2,
                                             float* __restrict__ outp) {
    extern __shared__ char sm[];
    uint32_t sbase = smem_u32(sm);
    uint32_t* xr_s = (uint32_t*)sm;                   // 2048 u32 (half2)
    float2*  att_s = (float2*)(sm + 8192);            // 2048 float2
    float*   logit_s = (float*)(sm + 90112);          // 8 edges x 4 heads
    float*   ssum = (float*)(sm + 90240);
    float*   ssq  = (float*)(sm + 90304);

    int n = blockIdx.x;
    int t = threadIdx.x;
    int lane = t & 31, wid = t >> 5;

    // stage xr row + att into smem
    const uint32_t* xrg = (const uint32_t*)d_xr + (size_t)n * 2048;
    const float2* attg = (const float2*)att;
    #pragma unroll
    for (int j = 0; j < 8; j++) {
        int idx = t + 256 * j;
        xr_s[idx] = xrg[idx];
        att_s[idx] = attg[idx];
    }
    __syncthreads();

    float2 acc[8];
    #pragma unroll
    for (int j = 0; j < 8; j++) acc[j] = make_float2(0.f, 0.f);
    float mh[4] = {-3.0e38f, -3.0e38f, -3.0e38f, -3.0e38f};
    float lh[4] = {0.f, 0.f, 0.f, 0.f};

    int beg = d_rowstart[n], end = d_rowstart[n + 1];
    for (int cs = beg; cs < end; cs += 8) {
        int chunkN = min(8, end - cs);
        // bulk async load of chunk's xl rows
        #pragma unroll
        for (int i = 0; i < 16; i++) {
            int id = t + i * 256;
            int e = id >> 9;
            if (e < chunkN) {
                int unit = id & 511;
                int src = d_esrc[cs + e];
                cp16(sbase + 24576 + e * 8192 + unit * 16,
                     (const char*)d_xl + (size_t)src * 8192 + unit * 16);
            }
        }
        asm volatile("cp.async.commit_group;" ::: "memory");
        asm volatile("cp.async.wait_group 0;" ::: "memory");
        __syncthreads();

        // phase A: warp-per-edge logits
        int e = wid;
        if (e < chunkN) {
            const uint32_t* xrow = (const uint32_t*)(sm + 24576 + e * 8192) + lane * 64;
            const uint32_t* xrp = xr_s + lane * 64;
            const float2* ap = att_s + lane * 64;
            float part = 0.f;
            #pragma unroll 16
            for (int k = 0; k < 64; k++) {
                float2 xl2 = __half22float2(*(const __half2*)&xrow[k]);
                float2 xr2 = __half22float2(*(const __half2*)&xrp[k]);
                float2 a2 = ap[k];
                float zx = xl2.x + xr2.x, zy = xl2.y + xr2.y;
                float lx = zx > 0.f ? zx : 0.2f * zx;
                float ly = zy > 0.f ? zy : 0.2f * zy;
                part += a2.x * lx + a2.y * ly;
            }
            part += __shfl_down_sync(0xffffffffu, part, 4, 8);
            part += __shfl_down_sync(0xffffffffu, part, 2, 8);
            part += __shfl_down_sync(0xffffffffu, part, 1, 8);
            if ((lane & 7) == 0) logit_s[e * 4 + (lane >> 3)] = part;
        }
        __syncthreads();

        // chunk softmax update (all threads redundantly)
        float cmax[4] = {-3.0e38f, -3.0e38f, -3.0e38f, -3.0e38f};
        for (int ee = 0; ee < chunkN; ee++) {
            #pragma unroll
            for (int h = 0; h < 4; h++)
                cmax[h] = fmaxf(cmax[h], logit_s[ee * 4 + h]);
        }
        float scl[4];
        #pragma unroll
        for (int h = 0; h < 4; h++) {
            float nm = fmaxf(mh[h], cmax[h]);
            scl[h] = __expf(mh[h] - nm);
            mh[h] = nm;
            lh[h] *= scl[h];
        }
        #pragma unroll
        for (int j = 0; j < 8; j++) {
            float s = scl[j >> 1];
            acc[j].x *= s; acc[j].y *= s;
        }
        // accumulate edges (no barriers, no shuffles)
        for (int ee = 0; ee < chunkN; ee++) {
            float cf[4];
            #pragma unroll
            for (int h = 0; h < 4; h++) {
                cf[h] = __expf(logit_s[ee * 4 + h] - mh[h]);
                lh[h] += cf[h] * 0.25f;     // counted 4x below? no — fix: add once
            }
            // correct l accumulation: undo the 0.25 trick — do it plainly
            #pragma unroll
            for (int h = 0; h < 4; h++) lh[h] += cf[h] * 0.75f;
            const uint32_t* xrow = (const uint32_t*)(sm + 24576 + ee * 8192);
            #pragma unroll
            for (int j = 0; j < 8; j++) {
                float2 x2 = __half22float2(*(const __half2*)&xrow[t + 256 * j]);
                float c = cf[j >> 1];
                acc[j].x += c * x2.x;
                acc[j].y += c * x2.y;
            }
        }
        __syncthreads();   // before next chunk overwrites xls
    }

    // epilogue: g = acc/l + bias_gat -> gs (aliases att_s region)
    float* gs = (float*)(sm + 8192);
    float rinv[4];
    #pragma unroll
    for (int h = 0; h < 4; h++) rinv[h] = 1.0f / lh[h];
    #pragma unroll
    for (int j = 0; j < 8; j++) {
        int f = 2 * t + 512 * j;
        float2 bgv = *(const float2*)(biasg + f);
        float2 g;
        g.x = acc[j].x * rinv[j >> 1] + bgv.x;
        g.y = acc[j].y * rinv[j >> 1] + bgv.y;
        *(float2*)(gs + f) = g;
    }
    if (t < 16) { ssum[t] = 0.f; ssq[t] = 0.f; }
    __syncthreads();

    // conv2: w2s aliases xls region
    float* w2s = (float*)(sm + 24576);
    for (int i = t; i < 1024; i += 256) w2s[i] = w2[i];
    __syncthreads();

    #pragma unroll
    for (int i = 0; i < 4; i++) {
        int oidx = t + 256 * i;
        int c = oidx >> 6, p = oidx & 63;
        float s = b2[c];
        #pragma unroll 16
        for (int ch = 0; ch < 64; ch++) s += w2s[c * 64 + ch] * gs[ch * 64 + p];
        outp[n * 1024 + oidx] = s;
        float vs = s, vq = s * s;
        #pragma unroll
        for (int off = 16; off > 0; off >>= 1) {
            vs += __shfl_down_sync(0xffffffffu, vs, off);
            vq += __shfl_down_sync(0xffffffffu, vq, off);
        }
        if (lane == 0) { atomicAdd(&ssum[c], vs); atomicAdd(&ssq[c], vq); }
    }
    __syncthreads();
    if (t < 16) {
        atomicAdd(&d_b2sum[t], ssum[t]);
        atomicAdd(&d_b2sq[t], ssq[t]);
    }
}

// ---------------- BN2 finalize + residual (merged) ----------------
__global__ void k_final(const float* __restrict__ x, float* __restrict__ o,
                        const float* __restrict__ g2, const float* __restrict__ be2) {
    __shared__ float sc[16], sh[16];
    int t = threadIdx.x;
    if (t < 16) {
        float mean = d_b2sum[t] * (1.0f / NPIX);
        float var = d_b2sq[t] * (1.0f / NPIX) - mean * mean;
        float s = g2[t] * rsqrtf(var + BNEPS);
        sc[t] = s;
        sh[t] = be2[t] - mean * s;
    }
    __syncthreads();
    int i = blockIdx.x * 256 + t;
    int c = (i >> 6) & 15;
    o[i] = o[i] * sc[c] + sh[c] + x[i];
}

// ---------------- launch (single stream, 5 kernels) ----------------
extern "C" void kernel_launch(void* const* d_in, const int* in_sizes, int n_in,
                              void* d_out, int out_size) {
    const float* x    = (const float*)d_in[0];
    const int*   ei   = (const int*)  d_in[1];
    const float* w1   = (const float*)d_in[2];
    const float* b1   = (const float*)d_in[3];
    const float* g1   = (const float*)d_in[4];
    const float* be1  = (const float*)d_in[5];
    const float* wl   = (const float*)d_in[6];
    const float* bl   = (const float*)d_in[7];
    const float* wr   = (const float*)d_in[8];
    const float* br   = (const float*)d_in[9];
    const float* att  = (const float*)d_in[10];
    const float* bg   = (const float*)d_in[11];
    const float* w2   = (const float*)d_in[12];
    const float* b2   = (const float*)d_in[13];
    const float* g2   = (const float*)d_in[14];
    const float* be2  = (const float*)d_in[15];
    float* outp = (float*)d_out;

    static int inited = 0;
    if (!inited) {
        cudaFuncSetAttribute(k_gemm, cudaFuncAttributeMaxDynamicSharedMemorySize, GSM_TOTAL);
        cudaFuncSetAttribute(k_gat, cudaFuncAttributeMaxDynamicSharedMemorySize, GAT_SMEM);
        inited = 1;
    }

    k_pre1<<<320, 256>>>(x, ei, w1, b1, g1, be1);
    k_pre3<<<8776, 256>>>(ei, x, wl, wr);
    dim3 gg(32, 16);
    k_gemm<<<gg, 512, GSM_TOTAL>>>(bl, br);
    k_gat<<<NN, 256, GAT_SMEM>>>(att, bg, w2, b2, outp);
    k_final<<<8192, 256>>>(x, outp, g2, be2);
}

// round 15
// speedup vs baseline: 1.4147x; 1.4147x over previous
#include <cuda_runtime.h>
#include <cuda_bf16.h>
#include <cuda_fp16.h>
#include <math.h>
#include <cstdint>

#define NN 2048
#define CC 16
#define FF 1024
#define NHEADS 4
#define KF 4096
#define EE 16384
#define NPIX 131072
#define BNEPS 1e-5f
#define KA 1024

// ---------------- scratch (static device memory; no allocation) ----------------
__device__ __half d_Af[NN * KA];
__device__ __half d_Blh[KF * KA];
__device__ __half d_Brh[KF * KA];
__device__ __half d_xl[NN * KF];
__device__ __half d_xr[NN * KF];
__device__ float d_Sx[16];
__device__ float d_Sxx[136];
__device__ float d_A[256];
__device__ float d_dv[16];
__device__ int   d_cnt[NN];
__device__ int   d_rowstart[NN + 1];
__device__ int   d_cursor[NN];
__device__ int   d_esrc[EE + NN];
__device__ float d_b2sum[16], d_b2sq[16];
__device__ int   d_tick;                          // zero at start; self-reset

// ---------------- helpers ----------------
__device__ __forceinline__ uint32_t smem_u32(const void* p) {
    uint32_t a;
    asm("{ .reg .u64 t; cvta.to.shared.u64 t, %1; cvt.u32.u64 %0, t; }" : "=r"(a) : "l"(p));
    return a;
}
__device__ __forceinline__ void cp16(uint32_t dst, const void* src) {
    asm volatile("cp.async.cg.shared.global [%0], [%1], 16;" :: "r"(dst), "l"(src) : "memory");
}
__device__ __forceinline__ void ldm4(uint32_t* r, uint32_t addr) {
    asm volatile("ldmatrix.sync.aligned.m8n8.x4.shared.b16 {%0,%1,%2,%3}, [%4];"
                 : "=r"(r[0]), "=r"(r[1]), "=r"(r[2]), "=r"(r[3]) : "r"(addr));
}
__device__ __forceinline__ void mma16816(float* d, const uint32_t* a, uint32_t b0, uint32_t b1) {
    asm volatile("mma.sync.aligned.m16n8k16.row.col.f32.f16.f16.f32 "
                 "{%0,%1,%2,%3}, {%4,%5,%6,%7}, {%8,%9}, {%0,%1,%2,%3};"
                 : "+f"(d[0]), "+f"(d[1]), "+f"(d[2]), "+f"(d[3])
                 : "r"(a[0]), "r"(a[1]), "r"(a[2]), "r"(a[3]), "r"(b0), "r"(b1));
}

// ---------------- pre1: stats (b<256) || hist (b<320); LAST block does bnfold + scan ----------------
__global__ __launch_bounds__(256) void k_pre1(const float* __restrict__ x,
                                              const int* __restrict__ ei,
                                              const float* __restrict__ w1, const float* __restrict__ b1,
                                              const float* __restrict__ g1, const float* __restrict__ be1) {
    int b = blockIdx.x;
    int t = threadIdx.x;
    if (b < 256) {
        __shared__ float sm[16][513];
        int base = b * 512;
        for (int i = t; i < 16 * 512; i += 256) {
            int c = i >> 9, s = i & 511;
            int q = base + s;
            sm[c][s] = x[(q >> 6) * 1024 + c * 64 + (q & 63)];
        }
        __syncthreads();
        if (t < 16) {
            float acc = 0.f;
            #pragma unroll 8
            for (int s = 0; s < 512; s++) acc += sm[t][s];
            atomicAdd(&d_Sx[t], acc);
        } else if (t < 152) {
            int p = t - 16;
            int c = 0, r = p;
            while (r >= 16 - c) { r -= 16 - c; c++; }
            int c2 = c + r;
            float acc = 0.f;
            #pragma unroll 8
            for (int s = 0; s < 512; s++) acc += sm[c][s] * sm[c2][s];
            atomicAdd(&d_Sxx[p], acc);
        }
    } else {
        int e = (b - 256) * 256 + t;
        if (e < EE) {
            int s = ei[e], d = ei[EE + e];
            if (s != d) atomicAdd(&d_cnt[d], 1);
        }
    }
    __shared__ int isLast;
    __syncthreads();
    if (t == 0) {
        __threadfence();
        int done = atomicAdd(&d_tick, 1);
        isLast = (done == 319);
        if (isLast) d_tick = 0;
    }
    __syncthreads();
    if (!isLast) return;
    __threadfence();

    {
        __shared__ float mx[16], cov[16][16];
        if (t < 16) mx[t] = d_Sx[t] * (1.0f / NPIX);
        __syncthreads();
        if (t < 136) {
            int c = 0, r = t;
            while (r >= 16 - c) { r -= 16 - c; c++; }
            int c2 = c + r;
            float cv = d_Sxx[t] * (1.0f / NPIX) - mx[c] * mx[c2];
            cov[c][c2] = cv; cov[c2][c] = cv;
        }
        __syncthreads();
        if (t < 16) d_Sx[t] = 0.f;
        if (t < 136) d_Sxx[t] = 0.f;
        int o = t >> 4, c = t & 15;
        float wc = w1[o * 16 + c];
        float pm = wc * mx[c];
        float pv = 0.f;
        #pragma unroll
        for (int c2 = 0; c2 < 16; c2++) pv += w1[o * 16 + c2] * cov[c][c2];
        pv *= wc;
        #pragma unroll
        for (int off = 8; off > 0; off >>= 1) {
            pm += __shfl_down_sync(0xffffffffu, pm, off, 16);
            pv += __shfl_down_sync(0xffffffffu, pv, off, 16);
        }
        float m = __shfl_sync(0xffffffffu, pm, (t & 16), 32) + b1[o];
        float var = __shfl_sync(0xffffffffu, pv, (t & 16), 32);
        float rs = rsqrtf(var + BNEPS) * g1[o];
        d_A[o * 16 + c] = wc * rs;
        if (c == 0) d_dv[o] = (b1[o] - m) * rs + be1[o];
    }
    __syncthreads();

    {
        __shared__ int wsum[8];
        int lane = t & 31, warp = t >> 5;
        int a[8], s = 0;
        #pragma unroll
        for (int k = 0; k < 8; k++) {
            a[k] = d_cnt[8 * t + k] + 1;
            s += a[k];
            d_cnt[8 * t + k] = 0;
        }
        int incl = s;
        #pragma unroll
        for (int off = 1; off < 32; off <<= 1) {
            int v = __shfl_up_sync(0xffffffffu, incl, off);
            if (lane >= off) incl += v;
        }
        if (lane == 31) wsum[warp] = incl;
        __syncthreads();
        if (t == 0) {
            int run = 0;
            #pragma unroll
            for (int w = 0; w < 8; w++) { run += wsum[w]; wsum[w] = run; }
        }
        __syncthreads();
        int base = (warp > 0) ? wsum[warp - 1] : 0;
        int running = base + incl - s;
        #pragma unroll
        for (int k = 0; k < 8; k++) {
            int idx = 8 * t + k;
            d_rowstart[idx] = running;
            d_cursor[idx] = running;
            running += a[k];
        }
        if (t == 255) d_rowstart[2048] = running;
    }
}

// ---------------- pre3: scatter (b<72) || yf (b<584) || convB wl (b<4680) || convB wr ----------------
__device__ __forceinline__ void convB_body(const float* __restrict__ w,
                                           __half* __restrict__ Bf,
                                           int bx, int by, int t) {
    __shared__ float ts[32][33];
    int nb = bx * 32;
    int kb = by * 32;
    int col = t & 31, trow = t >> 5;
    #pragma unroll
    for (int i = 0; i < 4; i++) {
        int r = trow + i * 8;
        ts[r][col] = w[(size_t)(kb + r) * 4096 + nb + col];
    }
    __syncthreads();
    int nloc = t >> 3, kq = (t & 7) * 4;
    __half hv[4];
    #pragma unroll
    for (int j = 0; j < 4; j++) hv[j] = __float2half(ts[kq + j][nloc]);
    size_t base = (size_t)(nb + nloc) * KA + kb + kq;
    *(uint2*)(Bf + base) = *(uint2*)hv;
}

__global__ __launch_bounds__(256) void k_pre3(const int* __restrict__ ei,
                                              const float* __restrict__ x,
                                              const float* __restrict__ wl,
                                              const float* __restrict__ wr) {
    int b = blockIdx.x;
    int t = threadIdx.x;
    if (b < 72) {
        if (b == 0 && t < 16) { d_b2sum[t] = 0.f; d_b2sq[t] = 0.f; }
        int i = b * 256 + t;
        if (i < NN) {
            int pos = atomicAdd(&d_cursor[i], 1);
            d_esrc[pos] = i;
        } else if (i < NN + EE) {
            int e = i - NN;
            int s = ei[e], d = ei[EE + e];
            if (s != d) { int pos = atomicAdd(&d_cursor[d], 1); d_esrc[pos] = s; }
        }
    } else if (b < 584) {
        __shared__ float As[256], dvs[16];
        if (t < 256) As[t] = d_A[t];
        if (t < 16) dvs[t] = d_dv[t];
        __syncthreads();
        int q = (b - 72) * 256 + t;
        int n = q >> 6, p = q & 63;
        float xv[16];
        #pragma unroll
        for (int c = 0; c < 16; c++) xv[c] = x[n * 1024 + c * 64 + p];
        #pragma unroll
        for (int o = 0; o < 16; o++) {
            float s = dvs[o];
            #pragma unroll
            for (int c = 0; c < 16; c++) s += As[o * 16 + c] * xv[c];
            int f = o * 64 + p;
            d_Af[(size_t)n * KA + f] = __float2half(s);
        }
    } else if (b < 4680) {
        int i = b - 584;
        convB_body(wl, d_Blh, i & 127, i >> 7, t);
    } else {
        int i = b - 4680;
        convB_body(wr, d_Brh, i & 127, i >> 7, t);
    }
}

// ---------------- mma.sync fp16 GEMM: 128x256 tile, 512 thr, K-chunk 128, 2-stage ----------------
#define STAGE_B 98304
#define GSM_TOTAL (2 * STAGE_B)

#define ISSUE_CHUNK(kb, buf) do {                                               \
    uint32_t sA_ = sbase + (buf) * STAGE_B;                                     \
    uint32_t sB_ = sA_ + 32768;                                                 \
    _Pragma("unroll")                                                           \
    for (int i_ = 0; i_ < 4; i_++) {                                            \
        int id_ = t + i_ * 512, r_ = id_ >> 4, c_ = id_ & 15;                   \
        cp16(sA_ + r_ * 256 + ((c_ >> 3) << 7) + ((((c_ & 7) ^ (r_ & 7))) << 4),\
             Ag + (size_t)r_ * KA + (kb) * 128 + c_ * 8);                       \
    }                                                                           \
    _Pragma("unroll")                                                           \
    for (int i_ = 0; i_ < 8; i_++) {                                            \
        int id_ = t + i_ * 512, r_ = id_ >> 4, c_ = id_ & 15;                   \
        cp16(sB_ + r_ * 256 + ((c_ >> 3) << 7) + ((((c_ & 7) ^ (r_ & 7))) << 4),\
             Bg + (size_t)r_ * KA + (kb) * 128 + c_ * 8);                       \
    }                                                                           \
    asm volatile("cp.async.commit_group;" ::: "memory");                        \
} while (0)

__global__ __launch_bounds__(512) void k_gemm(const float* __restrict__ biasl,
                                              const float* __restrict__ biasr) {
    extern __shared__ char smem[];
    uint32_t sbase = smem_u32(smem);
    int t = threadIdx.x, lane = t & 31, wid = t >> 5;
    int wm = wid & 3, wn = wid >> 2;
    int bm = blockIdx.y * 128;
    int bx = blockIdx.x;
    int isR = bx >= 16;
    int bn = (bx - (isR ? 16 : 0)) * 256;

    const __half* Ag = d_Af + (size_t)bm * KA;
    const __half* Bg = (isR ? d_Brh : d_Blh) + (size_t)bn * KA;
    const float* bias = isR ? biasr : biasl;
    __half* C = isR ? d_xr : d_xl;

    float acc[2][8][4];
    #pragma unroll
    for (int mi = 0; mi < 2; mi++)
        #pragma unroll
        for (int nj = 0; nj < 8; nj++)
            #pragma unroll
            for (int k = 0; k < 4; k++) acc[mi][nj][k] = 0.f;

    ISSUE_CHUNK(0, 0);
    ISSUE_CHUNK(1, 1);

    int g = lane >> 3, li = lane & 7;
    int arow = wm * 32 + (g & 1) * 8 + li;
    int brow = wn * 64 + (g >> 1) * 8 + li;
    int aun = (g >> 1);
    int bun = (g & 1);

    for (int kb = 0; kb < 8; kb++) {
        asm volatile("cp.async.wait_group 1;" ::: "memory");
        __syncthreads();
        uint32_t sA = sbase + (kb & 1) * STAGE_B;
        uint32_t sB = sA + 32768;
        #pragma unroll
        for (int ks = 0; ks < 8; ks++) {
            uint32_t af[2][4], bf[4][4];
            #pragma unroll
            for (int mi = 0; mi < 2; mi++) {
                int row = arow + mi * 16;
                int unit = ks * 2 + aun;
                ldm4(af[mi], sA + row * 256 + ((unit >> 3) << 7) + ((((unit & 7) ^ (row & 7))) << 4));
            }
            #pragma unroll
            for (int nt = 0; nt < 4; nt++) {
                int row = brow + nt * 16;
                int unit = ks * 2 + bun;
                ldm4(bf[nt], sB + row * 256 + ((unit >> 3) << 7) + ((((unit & 7) ^ (row & 7))) << 4));
            }
            #pragma unroll
            for (int mi = 0; mi < 2; mi++)
                #pragma unroll
                for (int nt = 0; nt < 4; nt++) {
                    mma16816(acc[mi][nt * 2 + 0], af[mi], bf[nt][0], bf[nt][1]);
                    mma16816(acc[mi][nt * 2 + 1], af[mi], bf[nt][2], bf[nt][3]);
                }
        }
        __syncthreads();
        if (kb + 2 < 8) { ISSUE_CHUNK(kb + 2, kb & 1); }
        else { asm volatile("cp.async.commit_group;" ::: "memory"); }
    }

    #pragma unroll
    for (int mi = 0; mi < 2; mi++) {
        int gm0 = bm + wm * 32 + mi * 16 + (lane >> 2);
        #pragma unroll
        for (int nj = 0; nj < 8; nj++) {
            int gn = bn + wn * 64 + nj * 8 + (lane & 3) * 2;
            float2 bv = *(const float2*)(bias + gn);
            __half2 h0 = __floats2half2_rn(acc[mi][nj][0] + bv.x, acc[mi][nj][1] + bv.y);
            __half2 h1 = __floats2half2_rn(acc[mi][nj][2] + bv.x, acc[mi][nj][3] + bv.y);
            *(__half2*)(C + (size_t)gm0 * 4096 + gn) = h0;
            *(__half2*)(C + (size_t)(gm0 + 8) * 4096 + gn) = h1;
        }
    }
}

// ---------------- fused GAT (pairwise edges, prefetched, 1 barrier / 2 edges) + conv2 + BN2 ----------------
__global__ __launch_bounds__(256) void k_gat(const float* __restrict__ att,
                                             const float* __restrict__ biasg,
                                             const float* __restrict__ w2,
                                             const float* __restrict__ b2,
                                             float* __restrict__ outp) {
    __shared__ float gs[4096];
    __shared__ float w2s[1024];
    __shared__ float red[2][8][8];     // [parity][warp][2 edges x 4 heads]
    __shared__ float ssum[16], ssq[16];
    int n = blockIdx.x;
    int t = threadIdx.x;
    int lane = t & 31, warp = t >> 5;

    for (int i = t; i < 1024; i += 256) w2s[i] = w2[i];
    if (t < 16) { ssum[t] = 0.f; ssq[t] = 0.f; }

    const __half2* xr2 = (const __half2*)d_xr + (size_t)n * 2048;
    float2 attv[8], xrv[8], acc[8];
    #pragma unroll
    for (int j = 0; j < 8; j++) {
        int f = 2 * t + 512 * j;
        attv[j] = *(const float2*)(att + f);
        xrv[j] = __half22float2(xr2[t + 256 * j]);
        acc[j] = make_float2(0.f, 0.f);
    }
    float mh[4] = {-3.0e38f, -3.0e38f, -3.0e38f, -3.0e38f};
    float lh[4] = {0.f, 0.f, 0.f, 0.f};

    int beg = d_rowstart[n], end = d_rowstart[n + 1];
    uint32_t cur0[8], cur1[8], nxt0[8], nxt1[8];
    {
        int s0 = d_esrc[beg];
        const uint32_t* p0 = (const uint32_t*)d_xl + (size_t)s0 * 2048;
        #pragma unroll
        for (int j = 0; j < 8; j++) cur0[j] = p0[t + 256 * j];
        if (beg + 1 < end) {
            int s1 = d_esrc[beg + 1];
            const uint32_t* p1 = (const uint32_t*)d_xl + (size_t)s1 * 2048;
            #pragma unroll
            for (int j = 0; j < 8; j++) cur1[j] = p1[t + 256 * j];
        } else {
            #pragma unroll
            for (int j = 0; j < 8; j++) cur1[j] = 0u;   // zero halves: 0*cf stays finite
        }
    }
    int pb = 0;
    for (int e = beg; e < end; e += 2) {
        int has1 = (e + 1 < end);
        // prefetch next pair (zero-fill absent edges to avoid Inf/NaN garbage)
        if (e + 2 < end) {
            int s0 = d_esrc[e + 2];
            const uint32_t* p0 = (const uint32_t*)d_xl + (size_t)s0 * 2048;
            #pragma unroll
            for (int j = 0; j < 8; j++) nxt0[j] = p0[t + 256 * j];
            if (e + 3 < end) {
                int s1 = d_esrc[e + 3];
                const uint32_t* p1 = (const uint32_t*)d_xl + (size_t)s1 * 2048;
                #pragma unroll
                for (int j = 0; j < 8; j++) nxt1[j] = p1[t + 256 * j];
            } else {
                #pragma unroll
                for (int j = 0; j < 8; j++) nxt1[j] = 0u;
            }
        } else {
            #pragma unroll
            for (int j = 0; j < 8; j++) { nxt0[j] = 0u; nxt1[j] = 0u; }
        }
        float2 x0[8], x1[8];
        #pragma unroll
        for (int j = 0; j < 8; j++) {
            x0[j] = __half22float2(*(__half2*)&cur0[j]);
            x1[j] = __half22float2(*(__half2*)&cur1[j]);
        }
        float part[8];
        #pragma unroll
        for (int h = 0; h < 8; h++) part[h] = 0.f;
        #pragma unroll
        for (int j = 0; j < 8; j++) {
            float2 a2 = attv[j], r2 = xrv[j];
            {
                float zx = x0[j].x + r2.x, zy = x0[j].y + r2.y;
                float lx = zx > 0.f ? zx : 0.2f * zx;
                float ly = zy > 0.f ? zy : 0.2f * zy;
                part[j >> 1] += a2.x * lx + a2.y * ly;
            }
            {
                float zx = x1[j].x + r2.x, zy = x1[j].y + r2.y;
                float lx = zx > 0.f ? zx : 0.2f * zx;
                float ly = zy > 0.f ? zy : 0.2f * zy;
                part[4 + (j >> 1)] += a2.x * lx + a2.y * ly;
            }
        }
        #pragma unroll
        for (int off = 16; off > 0; off >>= 1) {
            #pragma unroll
            for (int h = 0; h < 8; h++)
                part[h] += __shfl_down_sync(0xffffffffu, part[h], off);
        }
        if (lane == 0) {
            #pragma unroll
            for (int h = 0; h < 8; h++) red[pb][warp][h] = part[h];
        }
        __syncthreads();
        float L0[4], L1[4];
        #pragma unroll
        for (int h = 0; h < 4; h++) {
            float s0 = 0.f, s1 = 0.f;
            #pragma unroll
            for (int w = 0; w < 8; w++) { s0 += red[pb][w][h]; s1 += red[pb][w][4 + h]; }
            L0[h] = s0;
            L1[h] = has1 ? s1 : -3.0e38f;
        }
        float scl[4], cf0[4], cf1[4];
        #pragma unroll
        for (int h = 0; h < 4; h++) {
            float nm = fmaxf(mh[h], fmaxf(L0[h], L1[h]));
            scl[h] = __expf(mh[h] - nm);
            cf0[h] = __expf(L0[h] - nm);
            cf1[h] = has1 ? __expf(L1[h] - nm) : 0.f;
            mh[h] = nm;
            lh[h] = lh[h] * scl[h] + cf0[h] + cf1[h];
        }
        #pragma unroll
        for (int j = 0; j < 8; j++) {
            int h = j >> 1;
            acc[j].x = acc[j].x * scl[h] + cf0[h] * x0[j].x + cf1[h] * x1[j].x;
            acc[j].y = acc[j].y * scl[h] + cf0[h] * x0[j].y + cf1[h] * x1[j].y;
        }
        #pragma unroll
        for (int j = 0; j < 8; j++) { cur0[j] = nxt0[j]; cur1[j] = nxt1[j]; }
        pb ^= 1;
    }

    float rinv[4];
    #pragma unroll
    for (int h = 0; h < 4; h++) rinv[h] = 1.0f / lh[h];
    #pragma unroll
    for (int j = 0; j < 8; j++) {
        int f = 2 * t + 512 * j;
        int h = j >> 1;
        float2 bgv = *(const float2*)(biasg + f);
        float2 g;
        g.x = acc[j].x * rinv[h] + bgv.x;
        g.y = acc[j].y * rinv[h] + bgv.y;
        *(float2*)(gs + f) = g;
    }
    __syncthreads();

    #pragma unroll
    for (int i = 0; i < 4; i++) {
        int oidx = t + 256 * i;
        int c = oidx >> 6, p = oidx & 63;
        float s = b2[c];
        #pragma unroll 16
        for (int ch = 0; ch < 64; ch++) s += w2s[c * 64 + ch] * gs[ch * 64 + p];
        outp[n * 1024 + oidx] = s;
        float vs = s, vq = s * s;
        #pragma unroll
        for (int off = 16; off > 0; off >>= 1) {
            vs += __shfl_down_sync(0xffffffffu, vs, off);
            vq += __shfl_down_sync(0xffffffffu, vq, off);
        }
        if (lane == 0) { atomicAdd(&ssum[c], vs); atomicAdd(&ssq[c], vq); }
    }
    __syncthreads();
    if (t < 16) {
        atomicAdd(&d_b2sum[t], ssum[t]);
        atomicAdd(&d_b2sq[t], ssq[t]);
    }
}

// ---------------- BN2 finalize + residual (merged) ----------------
__global__ void k_final(const float* __restrict__ x, float* __restrict__ o,
                        const float* __restrict__ g2, const float* __restrict__ be2) {
    __shared__ float sc[16], sh[16];
    int t = threadIdx.x;
    if (t < 16) {
        float mean = d_b2sum[t] * (1.0f / NPIX);
        float var = d_b2sq[t] * (1.0f / NPIX) - mean * mean;
        float s = g2[t] * rsqrtf(var + BNEPS);
        sc[t] = s;
        sh[t] = be2[t] - mean * s;
    }
    __syncthreads();
    int i = blockIdx.x * 256 + t;
    int c = (i >> 6) & 15;
    o[i] = o[i] * sc[c] + sh[c] + x[i];
}

// ---------------- launch (single stream, 5 kernels) ----------------
extern "C" void kernel_launch(void* const* d_in, const int* in_sizes, int n_in,
                              void* d_out, int out_size) {
    const float* x    = (const float*)d_in[0];
    const int*   ei   = (const int*)  d_in[1];
    const float* w1   = (const float*)d_in[2];
    const float* b1   = (const float*)d_in[3];
    const float* g1   = (const float*)d_in[4];
    const float* be1  = (const float*)d_in[5];
    const float* wl   = (const float*)d_in[6];
    const float* bl   = (const float*)d_in[7];
    const float* wr   = (const float*)d_in[8];
    const float* br   = (const float*)d_in[9];
    const float* att  = (const float*)d_in[10];
    const float* bg   = (const float*)d_in[11];
    const float* w2   = (const float*)d_in[12];
    const float* b2   = (const float*)d_in[13];
    const float* g2   = (const float*)d_in[14];
    const float* be2  = (const float*)d_in[15];
    float* outp = (float*)d_out;

    static int inited = 0;
    if (!inited) {
        cudaFuncSetAttribute(k_gemm, cudaFuncAttributeMaxDynamicSharedMemorySize, GSM_TOTAL);
        inited = 1;
    }

    k_pre1<<<320, 256>>>(x, ei, w1, b1, g1, be1);
    k_pre3<<<8776, 256>>>(ei, x, wl, wr);
    dim3 gg(32, 16);
    k_gemm<<<gg, 512, GSM_TOTAL>>>(bl, br);
    k_gat<<<NN, 256>>>(att, bg, w2, b2, outp);
    k_final<<<8192, 256>>>(x, outp, g2, be2);
}

// round 16
// speedup vs baseline: 1.5328x; 1.0835x over previous
#include <cuda_runtime.h>
#include <cuda_bf16.h>
#include <cuda_fp16.h>
#include <math.h>
#include <cstdint>

#define NN 2048
#define CC 16
#define FF 1024
#define NHEADS 4
#define KF 4096
#define EE 16384
#define NPIX 131072
#define BNEPS 1e-5f
#define KA 1024

// ---------------- scratch (static device memory; no allocation) ----------------
__device__ __half d_Af[NN * KA];
__device__ __half d_Blh[KF * KA];
__device__ __half d_Brh[KF * KA];
__device__ __half d_xl[NN * KF];
__device__ __half d_xr[NN * KF];
__device__ float d_Sx[16];
__device__ float d_Sxx[136];
__device__ float d_A[256];
__device__ float d_dv[16];
__device__ int   d_cnt[NN];
__device__ int   d_rowstart[NN + 1];
__device__ int   d_cursor[NN];
__device__ int   d_esrc[EE + NN];
__device__ float d_b2sum[16], d_b2sq[16];
__device__ int   d_tick;                          // zero at start; self-reset

// ---------------- helpers ----------------
__device__ __forceinline__ uint32_t smem_u32(const void* p) {
    uint32_t a;
    asm("{ .reg .u64 t; cvta.to.shared.u64 t, %1; cvt.u32.u64 %0, t; }" : "=r"(a) : "l"(p));
    return a;
}
__device__ __forceinline__ void cp16(uint32_t dst, const void* src) {
    asm volatile("cp.async.cg.shared.global [%0], [%1], 16;" :: "r"(dst), "l"(src) : "memory");
}
__device__ __forceinline__ void ldm4(uint32_t* r, uint32_t addr) {
    asm volatile("ldmatrix.sync.aligned.m8n8.x4.shared.b16 {%0,%1,%2,%3}, [%4];"
                 : "=r"(r[0]), "=r"(r[1]), "=r"(r[2]), "=r"(r[3]) : "r"(addr));
}
__device__ __forceinline__ void mma16816(float* d, const uint32_t* a, uint32_t b0, uint32_t b1) {
    asm volatile("mma.sync.aligned.m16n8k16.row.col.f32.f16.f16.f32 "
                 "{%0,%1,%2,%3}, {%4,%5,%6,%7}, {%8,%9}, {%0,%1,%2,%3};"
                 : "+f"(d[0]), "+f"(d[1]), "+f"(d[2]), "+f"(d[3])
                 : "r"(a[0]), "r"(a[1]), "r"(a[2]), "r"(a[3]), "r"(b0), "r"(b1));
}

// ---------------- pre1: stats (b<256) || hist (b<320); LAST block does bnfold + scan ----------------
__global__ __launch_bounds__(256) void k_pre1(const float* __restrict__ x,
                                              const int* __restrict__ ei,
                                              const float* __restrict__ w1, const float* __restrict__ b1,
                                              const float* __restrict__ g1, const float* __restrict__ be1) {
    int b = blockIdx.x;
    int t = threadIdx.x;
    if (b < 256) {
        __shared__ float sm[16][513];
        int base = b * 512;
        for (int i = t; i < 16 * 512; i += 256) {
            int c = i >> 9, s = i & 511;
            int q = base + s;
            sm[c][s] = x[(q >> 6) * 1024 + c * 64 + (q & 63)];
        }
        __syncthreads();
        if (t < 16) {
            float acc = 0.f;
            #pragma unroll 8
            for (int s = 0; s < 512; s++) acc += sm[t][s];
            atomicAdd(&d_Sx[t], acc);
        } else if (t < 152) {
            int p = t - 16;
            int c = 0, r = p;
            while (r >= 16 - c) { r -= 16 - c; c++; }
            int c2 = c + r;
            float acc = 0.f;
            #pragma unroll 8
            for (int s = 0; s < 512; s++) acc += sm[c][s] * sm[c2][s];
            atomicAdd(&d_Sxx[p], acc);
        }
    } else {
        int e = (b - 256) * 256 + t;
        if (e < EE) {
            int s = ei[e], d = ei[EE + e];
            if (s != d) atomicAdd(&d_cnt[d], 1);
        }
    }
    __shared__ int isLast;
    __syncthreads();
    if (t == 0) {
        __threadfence();
        int done = atomicAdd(&d_tick, 1);
        isLast = (done == 319);
        if (isLast) d_tick = 0;
    }
    __syncthreads();
    if (!isLast) return;
    __threadfence();

    {
        __shared__ float mx[16], cov[16][16];
        if (t < 16) mx[t] = d_Sx[t] * (1.0f / NPIX);
        __syncthreads();
        if (t < 136) {
            int c = 0, r = t;
            while (r >= 16 - c) { r -= 16 - c; c++; }
            int c2 = c + r;
            float cv = d_Sxx[t] * (1.0f / NPIX) - mx[c] * mx[c2];
            cov[c][c2] = cv; cov[c2][c] = cv;
        }
        __syncthreads();
        if (t < 16) d_Sx[t] = 0.f;
        if (t < 136) d_Sxx[t] = 0.f;
        int o = t >> 4, c = t & 15;
        float wc = w1[o * 16 + c];
        float pm = wc * mx[c];
        float pv = 0.f;
        #pragma unroll
        for (int c2 = 0; c2 < 16; c2++) pv += w1[o * 16 + c2] * cov[c][c2];
        pv *= wc;
        #pragma unroll
        for (int off = 8; off > 0; off >>= 1) {
            pm += __shfl_down_sync(0xffffffffu, pm, off, 16);
            pv += __shfl_down_sync(0xffffffffu, pv, off, 16);
        }
        float m = __shfl_sync(0xffffffffu, pm, (t & 16), 32) + b1[o];
        float var = __shfl_sync(0xffffffffu, pv, (t & 16), 32);
        float rs = rsqrtf(var + BNEPS) * g1[o];
        d_A[o * 16 + c] = wc * rs;
        if (c == 0) d_dv[o] = (b1[o] - m) * rs + be1[o];
    }
    __syncthreads();

    {
        __shared__ int wsum[8];
        int lane = t & 31, warp = t >> 5;
        int a[8], s = 0;
        #pragma unroll
        for (int k = 0; k < 8; k++) {
            a[k] = d_cnt[8 * t + k] + 1;
            s += a[k];
            d_cnt[8 * t + k] = 0;
        }
        int incl = s;
        #pragma unroll
        for (int off = 1; off < 32; off <<= 1) {
            int v = __shfl_up_sync(0xffffffffu, incl, off);
            if (lane >= off) incl += v;
        }
        if (lane == 31) wsum[warp] = incl;
        __syncthreads();
        if (t == 0) {
            int run = 0;
            #pragma unroll
            for (int w = 0; w < 8; w++) { run += wsum[w]; wsum[w] = run; }
        }
        __syncthreads();
        int base = (warp > 0) ? wsum[warp - 1] : 0;
        int running = base + incl - s;
        #pragma unroll
        for (int k = 0; k < 8; k++) {
            int idx = 8 * t + k;
            d_rowstart[idx] = running;
            d_cursor[idx] = running;
            running += a[k];
        }
        if (t == 255) d_rowstart[2048] = running;
    }
}

// ---------------- pre3: scatter (b<72) || yf (b<584) || convB wl (b<4680) || convB wr ----------------
__device__ __forceinline__ void convB_body(const float* __restrict__ w,
                                           __half* __restrict__ Bf,
                                           int bx, int by, int t) {
    __shared__ float ts[32][33];
    int nb = bx * 32;
    int kb = by * 32;
    int col = t & 31, trow = t >> 5;
    #pragma unroll
    for (int i = 0; i < 4; i++) {
        int r = trow + i * 8;
        ts[r][col] = w[(size_t)(kb + r) * 4096 + nb + col];
    }
    __syncthreads();
    int nloc = t >> 3, kq = (t & 7) * 4;
    __half hv[4];
    #pragma unroll
    for (int j = 0; j < 4; j++) hv[j] = __float2half(ts[kq + j][nloc]);
    size_t base = (size_t)(nb + nloc) * KA + kb + kq;
    *(uint2*)(Bf + base) = *(uint2*)hv;
}

__global__ __launch_bounds__(256) void k_pre3(const int* __restrict__ ei,
                                              const float* __restrict__ x,
                                              const float* __restrict__ wl,
                                              const float* __restrict__ wr) {
    int b = blockIdx.x;
    int t = threadIdx.x;
    if (b < 72) {
        if (b == 0 && t < 16) { d_b2sum[t] = 0.f; d_b2sq[t] = 0.f; }
        int i = b * 256 + t;
        if (i < NN) {
            int pos = atomicAdd(&d_cursor[i], 1);
            d_esrc[pos] = i;
        } else if (i < NN + EE) {
            int e = i - NN;
            int s = ei[e], d = ei[EE + e];
            if (s != d) { int pos = atomicAdd(&d_cursor[d], 1); d_esrc[pos] = s; }
        }
    } else if (b < 584) {
        __shared__ float As[256], dvs[16];
        if (t < 256) As[t] = d_A[t];
        if (t < 16) dvs[t] = d_dv[t];
        __syncthreads();
        int q = (b - 72) * 256 + t;
        int n = q >> 6, p = q & 63;
        float xv[16];
        #pragma unroll
        for (int c = 0; c < 16; c++) xv[c] = x[n * 1024 + c * 64 + p];
        #pragma unroll
        for (int o = 0; o < 16; o++) {
            float s = dvs[o];
            #pragma unroll
            for (int c = 0; c < 16; c++) s += As[o * 16 + c] * xv[c];
            int f = o * 64 + p;
            d_Af[(size_t)n * KA + f] = __float2half(s);
        }
    } else if (b < 4680) {
        int i = b - 584;
        convB_body(wl, d_Blh, i & 127, i >> 7, t);
    } else {
        int i = b - 4680;
        convB_body(wr, d_Brh, i & 127, i >> 7, t);
    }
}

// ---------------- mma.sync fp16 GEMM: 128x256 tile, 512 thr, K-chunk 128, 2-stage ----------------
#define STAGE_B 98304
#define GSM_TOTAL (2 * STAGE_B)

#define ISSUE_CHUNK(kb, buf) do {                                               \
    uint32_t sA_ = sbase + (buf) * STAGE_B;                                     \
    uint32_t sB_ = sA_ + 32768;                                                 \
    _Pragma("unroll")                                                           \
    for (int i_ = 0; i_ < 4; i_++) {                                            \
        int id_ = t + i_ * 512, r_ = id_ >> 4, c_ = id_ & 15;                   \
        cp16(sA_ + r_ * 256 + ((c_ >> 3) << 7) + ((((c_ & 7) ^ (r_ & 7))) << 4),\
             Ag + (size_t)r_ * KA + (kb) * 128 + c_ * 8);                       \
    }                                                                           \
    _Pragma("unroll")                                                           \
    for (int i_ = 0; i_ < 8; i_++) {                                            \
        int id_ = t + i_ * 512, r_ = id_ >> 4, c_ = id_ & 15;                   \
        cp16(sB_ + r_ * 256 + ((c_ >> 3) << 7) + ((((c_ & 7) ^ (r_ & 7))) << 4),\
             Bg + (size_t)r_ * KA + (kb) * 128 + c_ * 8);                       \
    }                                                                           \
    asm volatile("cp.async.commit_group;" ::: "memory");                        \
} while (0)

__global__ __launch_bounds__(512) void k_gemm(const float* __restrict__ biasl,
                                              const float* __restrict__ biasr) {
    extern __shared__ char smem[];
    uint32_t sbase = smem_u32(smem);
    int t = threadIdx.x, lane = t & 31, wid = t >> 5;
    int wm = wid & 3, wn = wid >> 2;
    int bm = blockIdx.y * 128;
    int bx = blockIdx.x;
    int isR = bx >= 16;
    int bn = (bx - (isR ? 16 : 0)) * 256;

    const __half* Ag = d_Af + (size_t)bm * KA;
    const __half* Bg = (isR ? d_Brh : d_Blh) + (size_t)bn * KA;
    const float* bias = isR ? biasr : biasl;
    __half* C = isR ? d_xr : d_xl;

    float acc[2][8][4];
    #pragma unroll
    for (int mi = 0; mi < 2; mi++)
        #pragma unroll
        for (int nj = 0; nj < 8; nj++)
            #pragma unroll
            for (int k = 0; k < 4; k++) acc[mi][nj][k] = 0.f;

    ISSUE_CHUNK(0, 0);
    ISSUE_CHUNK(1, 1);

    int g = lane >> 3, li = lane & 7;
    int arow = wm * 32 + (g & 1) * 8 + li;
    int brow = wn * 64 + (g >> 1) * 8 + li;
    int aun = (g >> 1);
    int bun = (g & 1);

    for (int kb = 0; kb < 8; kb++) {
        asm volatile("cp.async.wait_group 1;" ::: "memory");
        __syncthreads();
        uint32_t sA = sbase + (kb & 1) * STAGE_B;
        uint32_t sB = sA + 32768;
        #pragma unroll
        for (int ks = 0; ks < 8; ks++) {
            uint32_t af[2][4], bf[4][4];
            #pragma unroll
            for (int mi = 0; mi < 2; mi++) {
                int row = arow + mi * 16;
                int unit = ks * 2 + aun;
                ldm4(af[mi], sA + row * 256 + ((unit >> 3) << 7) + ((((unit & 7) ^ (row & 7))) << 4));
            }
            #pragma unroll
            for (int nt = 0; nt < 4; nt++) {
                int row = brow + nt * 16;
                int unit = ks * 2 + bun;
                ldm4(bf[nt], sB + row * 256 + ((unit >> 3) << 7) + ((((unit & 7) ^ (row & 7))) << 4));
            }
            #pragma unroll
            for (int mi = 0; mi < 2; mi++)
                #pragma unroll
                for (int nt = 0; nt < 4; nt++) {
                    mma16816(acc[mi][nt * 2 + 0], af[mi], bf[nt][0], bf[nt][1]);
                    mma16816(acc[mi][nt * 2 + 1], af[mi], bf[nt][2], bf[nt][3]);
                }
        }
        __syncthreads();
        if (kb + 2 < 8) { ISSUE_CHUNK(kb + 2, kb & 1); }
        else { asm volatile("cp.async.commit_group;" ::: "memory"); }
    }

    #pragma unroll
    for (int mi = 0; mi < 2; mi++) {
        int gm0 = bm + wm * 32 + mi * 16 + (lane >> 2);
        #pragma unroll
        for (int nj = 0; nj < 8; nj++) {
            int gn = bn + wn * 64 + nj * 8 + (lane & 3) * 2;
            float2 bv = *(const float2*)(bias + gn);
            __half2 h0 = __floats2half2_rn(acc[mi][nj][0] + bv.x, acc[mi][nj][1] + bv.y);
            __half2 h1 = __floats2half2_rn(acc[mi][nj][2] + bv.x, acc[mi][nj][3] + bv.y);
            *(__half2*)(C + (size_t)gm0 * 4096 + gn) = h0;
            *(__half2*)(C + (size_t)(gm0 + 8) * 4096 + gn) = h1;
        }
    }
}

// ---------------- fused GAT: head-aligned vectorized, pairwise edges + conv2 + BN2 ----------------
// thread t owns half2 idx [4t..4t+3] (head h0=t>>7) and [1024+4t..1024+4t+3] (head h0+2)
__device__ __forceinline__ float2 h2f(uint32_t u) { return __half22float2(*(__half2*)&u); }

__global__ __launch_bounds__(256) void k_gat(const float* __restrict__ att,
                                             const float* __restrict__ biasg,
                                             const float* __restrict__ w2,
                                             const float* __restrict__ b2,
                                             float* __restrict__ outp) {
    __shared__ float gs[4096];
    __shared__ float w2s[1024];
    __shared__ float4 red4[2][8];   // [parity][warp] = {e0_slotA, e0_slotB, e1_slotA, e1_slotB}
    __shared__ float ssum[16], ssq[16];
    int n = blockIdx.x;
    int t = threadIdx.x;
    int lane = t & 31, warp = t >> 5;
    int hsel = t >> 7;                     // warps 0-3: heads 0/2 ; warps 4-7: heads 1/3

    for (int i = t; i < 1024; i += 256) w2s[i] = w2[i];
    if (t < 16) { ssum[t] = 0.f; ssq[t] = 0.f; }

    const uint4* xrg = (const uint4*)((const __half*)d_xr + (size_t)n * 4096);
    uint4 xru0 = xrg[t], xru1 = xrg[256 + t];
    const float4* attf = (const float4*)att;
    float4 aq0 = attf[2 * t], aq1 = attf[2 * t + 1];
    float4 aq2 = attf[512 + 2 * t], aq3 = attf[512 + 2 * t + 1];
    float2 xrv[8], attv[8];
    xrv[0] = h2f(xru0.x); xrv[1] = h2f(xru0.y); xrv[2] = h2f(xru0.z); xrv[3] = h2f(xru0.w);
    xrv[4] = h2f(xru1.x); xrv[5] = h2f(xru1.y); xrv[6] = h2f(xru1.z); xrv[7] = h2f(xru1.w);
    attv[0] = make_float2(aq0.x, aq0.y); attv[1] = make_float2(aq0.z, aq0.w);
    attv[2] = make_float2(aq1.x, aq1.y); attv[3] = make_float2(aq1.z, aq1.w);
    attv[4] = make_float2(aq2.x, aq2.y); attv[5] = make_float2(aq2.z, aq2.w);
    attv[6] = make_float2(aq3.x, aq3.y); attv[7] = make_float2(aq3.z, aq3.w);

    float2 acc[8];
    #pragma unroll
    for (int k = 0; k < 8; k++) acc[k] = make_float2(0.f, 0.f);
    float mh_a = -3.0e38f, mh_b = -3.0e38f, lh_a = 0.f, lh_b = 0.f;

    int beg = d_rowstart[n], end = d_rowstart[n + 1];
    uint4 zero4 = make_uint4(0u, 0u, 0u, 0u);
    uint4 c0a, c0b, c1a, c1b, n0a, n0b, n1a, n1b;
    {
        int s0 = d_esrc[beg];
        const uint4* p0 = (const uint4*)((const __half*)d_xl + (size_t)s0 * 4096);
        c0a = p0[t]; c0b = p0[256 + t];
        if (beg + 1 < end) {
            int s1 = d_esrc[beg + 1];
            const uint4* p1 = (const uint4*)((const __half*)d_xl + (size_t)s1 * 4096);
            c1a = p1[t]; c1b = p1[256 + t];
        } else { c1a = zero4; c1b = zero4; }
    }
    int pb = 0;
    for (int e = beg; e < end; e += 2) {
        int has1 = (e + 1 < end);
        if (e + 2 < end) {
            int s0 = d_esrc[e + 2];
            const uint4* p0 = (const uint4*)((const __half*)d_xl + (size_t)s0 * 4096);
            n0a = p0[t]; n0b = p0[256 + t];
            if (e + 3 < end) {
                int s1 = d_esrc[e + 3];
                const uint4* p1 = (const uint4*)((const __half*)d_xl + (size_t)s1 * 4096);
                n1a = p1[t]; n1b = p1[256 + t];
            } else { n1a = zero4; n1b = zero4; }
        } else { n0a = zero4; n0b = zero4; n1a = zero4; n1b = zero4; }

        float2 x0[8], x1[8];
        x0[0] = h2f(c0a.x); x0[1] = h2f(c0a.y); x0[2] = h2f(c0a.z); x0[3] = h2f(c0a.w);
        x0[4] = h2f(c0b.x); x0[5] = h2f(c0b.y); x0[6] = h2f(c0b.z); x0[7] = h2f(c0b.w);
        x1[0] = h2f(c1a.x); x1[1] = h2f(c1a.y); x1[2] = h2f(c1a.z); x1[3] = h2f(c1a.w);
        x1[4] = h2f(c1b.x); x1[5] = h2f(c1b.y); x1[6] = h2f(c1b.z); x1[7] = h2f(c1b.w);

        float p00 = 0.f, p01 = 0.f, p10 = 0.f, p11 = 0.f;
        #pragma unroll
        for (int k = 0; k < 4; k++) {
            float2 a2 = attv[k], r2 = xrv[k];
            float zx = x0[k].x + r2.x, zy = x0[k].y + r2.y;
            p00 += a2.x * (zx > 0.f ? zx : 0.2f * zx) + a2.y * (zy > 0.f ? zy : 0.2f * zy);
            zx = x1[k].x + r2.x; zy = x1[k].y + r2.y;
            p10 += a2.x * (zx > 0.f ? zx : 0.2f * zx) + a2.y * (zy > 0.f ? zy : 0.2f * zy);
        }
        #pragma unroll
        for (int k = 4; k < 8; k++) {
            float2 a2 = attv[k], r2 = xrv[k];
            float zx = x0[k].x + r2.x, zy = x0[k].y + r2.y;
            p01 += a2.x * (zx > 0.f ? zx : 0.2f * zx) + a2.y * (zy > 0.f ? zy : 0.2f * zy);
            zx = x1[k].x + r2.x; zy = x1[k].y + r2.y;
            p11 += a2.x * (zx > 0.f ? zx : 0.2f * zx) + a2.y * (zy > 0.f ? zy : 0.2f * zy);
        }
        #pragma unroll
        for (int off = 16; off > 0; off >>= 1) {
            p00 += __shfl_down_sync(0xffffffffu, p00, off);
            p01 += __shfl_down_sync(0xffffffffu, p01, off);
            p10 += __shfl_down_sync(0xffffffffu, p10, off);
            p11 += __shfl_down_sync(0xffffffffu, p11, off);
        }
        if (lane == 0) red4[pb][warp] = make_float4(p00, p01, p10, p11);
        __syncthreads();

        const float4* rr = &red4[pb][hsel * 4];
        float4 r0 = rr[0], r1 = rr[1], r2q = rr[2], r3q = rr[3];
        float L0a = r0.x + r1.x + r2q.x + r3q.x;
        float L0b = r0.y + r1.y + r2q.y + r3q.y;
        float L1a = has1 ? (r0.z + r1.z + r2q.z + r3q.z) : -3.0e38f;
        float L1b = has1 ? (r0.w + r1.w + r2q.w + r3q.w) : -3.0e38f;

        float nma = fmaxf(mh_a, fmaxf(L0a, L1a));
        float nmb = fmaxf(mh_b, fmaxf(L0b, L1b));
        float sa = __expf(mh_a - nma), sb = __expf(mh_b - nmb);
        float ca0 = __expf(L0a - nma), cb0 = __expf(L0b - nmb);
        float ca1 = has1 ? __expf(L1a - nma) : 0.f;
        float cb1 = has1 ? __expf(L1b - nmb) : 0.f;
        mh_a = nma; mh_b = nmb;
        lh_a = lh_a * sa + ca0 + ca1;
        lh_b = lh_b * sb + cb0 + cb1;
        #pragma unroll
        for (int k = 0; k < 4; k++) {
            acc[k].x = acc[k].x * sa + ca0 * x0[k].x + ca1 * x1[k].x;
            acc[k].y = acc[k].y * sa + ca0 * x0[k].y + ca1 * x1[k].y;
        }
        #pragma unroll
        for (int k = 4; k < 8; k++) {
            acc[k].x = acc[k].x * sb + cb0 * x0[k].x + cb1 * x1[k].x;
            acc[k].y = acc[k].y * sb + cb0 * x0[k].y + cb1 * x1[k].y;
        }
        c0a = n0a; c0b = n0b; c1a = n1a; c1b = n1b;
        pb ^= 1;
    }

    float rinva = 1.0f / lh_a, rinvb = 1.0f / lh_b;
    const float4* bgf = (const float4*)biasg;
    float4 b0 = bgf[2 * t], b1q = bgf[2 * t + 1];
    float4 b2q = bgf[512 + 2 * t], b3q = bgf[512 + 2 * t + 1];
    float4 o0 = make_float4(acc[0].x * rinva + b0.x, acc[0].y * rinva + b0.y,
                            acc[1].x * rinva + b0.z, acc[1].y * rinva + b0.w);
    float4 o1 = make_float4(acc[2].x * rinva + b1q.x, acc[2].y * rinva + b1q.y,
                            acc[3].x * rinva + b1q.z, acc[3].y * rinva + b1q.w);
    float4 o2 = make_float4(acc[4].x * rinvb + b2q.x, acc[4].y * rinvb + b2q.y,
                            acc[5].x * rinvb + b2q.z, acc[5].y * rinvb + b2q.w);
    float4 o3 = make_float4(acc[6].x * rinvb + b3q.x, acc[6].y * rinvb + b3q.y,
                            acc[7].x * rinvb + b3q.z, acc[7].y * rinvb + b3q.w);
    *(float4*)(gs + 8 * t) = o0;
    *(float4*)(gs + 8 * t + 4) = o1;
    *(float4*)(gs + 2048 + 8 * t) = o2;
    *(float4*)(gs + 2048 + 8 * t + 4) = o3;
    __syncthreads();

    #pragma unroll
    for (int i = 0; i < 4; i++) {
        int oidx = t + 256 * i;
        int c = oidx >> 6, p = oidx & 63;
        float s = b2[c];
        #pragma unroll 16
        for (int ch = 0; ch < 64; ch++) s += w2s[c * 64 + ch] * gs[ch * 64 + p];
        outp[n * 1024 + oidx] = s;
        float vs = s, vq = s * s;
        #pragma unroll
        for (int off = 16; off > 0; off >>= 1) {
            vs += __shfl_down_sync(0xffffffffu, vs, off);
            vq += __shfl_down_sync(0xffffffffu, vq, off);
        }
        if (lane == 0) { atomicAdd(&ssum[c], vs); atomicAdd(&ssq[c], vq); }
    }
    __syncthreads();
    if (t < 16) {
        atomicAdd(&d_b2sum[t], ssum[t]);
        atomicAdd(&d_b2sq[t], ssq[t]);
    }
}

// ---------------- BN2 finalize + residual (merged) ----------------
__global__ void k_final(const float* __restrict__ x, float* __restrict__ o,
                        const float* __restrict__ g2, const float* __restrict__ be2) {
    __shared__ float sc[16], sh[16];
    int t = threadIdx.x;
    if (t < 16) {
        float mean = d_b2sum[t] * (1.0f / NPIX);
        float var = d_b2sq[t] * (1.0f / NPIX) - mean * mean;
        float s = g2[t] * rsqrtf(var + BNEPS);
        sc[t] = s;
        sh[t] = be2[t] - mean * s;
    }
    __syncthreads();
    int i = blockIdx.x * 256 + t;
    int c = (i >> 6) & 15;
    o[i] = o[i] * sc[c] + sh[c] + x[i];
}

// ---------------- launch (single stream, 5 kernels) ----------------
extern "C" void kernel_launch(void* const* d_in, const int* in_sizes, int n_in,
                              void* d_out, int out_size) {
    const float* x    = (const float*)d_in[0];
    const int*   ei   = (const int*)  d_in[1];
    const float* w1   = (const float*)d_in[2];
    const float* b1   = (const float*)d_in[3];
    const float* g1   = (const float*)d_in[4];
    const float* be1  = (const float*)d_in[5];
    const float* wl   = (const float*)d_in[6];
    const float* bl   = (const float*)d_in[7];
    const float* wr   = (const float*)d_in[8];
    const float* br   = (const float*)d_in[9];
    const float* att  = (const float*)d_in[10];
    const float* bg   = (const float*)d_in[11];
    const float* w2   = (const float*)d_in[12];
    const float* b2   = (const float*)d_in[13];
    const float* g2   = (const float*)d_in[14];
    const float* be2  = (const float*)d_in[15];
    float* outp = (float*)d_out;

    static int inited = 0;
    if (!inited) {
        cudaFuncSetAttribute(k_gemm, cudaFuncAttributeMaxDynamicSharedMemorySize, GSM_TOTAL);
        inited = 1;
    }

    k_pre1<<<320, 256>>>(x, ei, w1, b1, g1, be1);
    k_pre3<<<8776, 256>>>(ei, x, wl, wr);
    dim3 gg(32, 16);
    k_gemm<<<gg, 512, GSM_TOTAL>>>(bl, br);
    k_gat<<<NN, 256>>>(att, bg, w2, b2, outp);
    k_final<<<8192, 256>>>(x, outp, g2, be2);
}